// round 8
// baseline (speedup 1.0000x reference)
#include <cuda_runtime.h>

#define BB 32
#define CC 448
#define HWI 32
#define PIN 1024       // 32*32
#define HWF 64
#define NPOS 4096
#define DP 100
#define DPAD 104
#define OHW 256
#define CCHUNK 20
#define NCHUNK 5

// ---- packed f32x2 helpers (sm_103a) ----
__device__ __forceinline__ unsigned long long pack2(float lo, float hi) {
    unsigned long long r;
    asm("mov.b64 %0, {%1, %2};" : "=l"(r) : "f"(lo), "f"(hi));
    return r;
}
__device__ __forceinline__ float2 unpack2(unsigned long long v) {
    float lo, hi;
    asm("mov.b64 {%0, %1}, %2;" : "=f"(lo), "=f"(hi) : "l"(v));
    return make_float2(lo, hi);
}
__device__ __forceinline__ unsigned long long fma2(unsigned long long a,
                                                   unsigned long long b,
                                                   unsigned long long c) {
    unsigned long long d;
    asm("fma.rn.f32x2 %0, %1, %2, %3;" : "=l"(d) : "l"(a), "l"(b), "l"(c));
    return d;
}
__device__ __forceinline__ void mbar_init(unsigned int mbar, unsigned int cnt) {
    asm volatile("mbarrier.init.shared.b64 [%0], %1;" :: "r"(mbar), "r"(cnt) : "memory");
}
__device__ __forceinline__ void mbar_expect_tx(unsigned int mbar, unsigned int bytes) {
    asm volatile("mbarrier.arrive.expect_tx.shared.b64 _, [%0], %1;"
                 :: "r"(mbar), "r"(bytes) : "memory");
}
__device__ __forceinline__ void bulk_g2s(unsigned int sdst, const void* gsrc,
                                         unsigned int bytes, unsigned int mbar) {
    asm volatile("cp.async.bulk.shared::cta.global.mbarrier::complete_tx::bytes "
                 "[%0], [%1], %2, [%3];"
                 :: "r"(sdst), "l"(gsrc), "r"(bytes), "r"(mbar) : "memory");
}
__device__ __forceinline__ void mbar_wait(unsigned int mbar, unsigned int parity) {
    asm volatile(
        "{\n\t.reg .pred P;\n\t"
        "WAIT_%=:\n\t"
        "mbarrier.try_wait.parity.acquire.cta.shared::cta.b64 P, [%0], %1, 0x989680;\n\t"
        "@P bra.uni DONE_%=;\n\t"
        "bra.uni WAIT_%=;\n\t"
        "DONE_%=:\n\t}"
        :: "r"(mbar), "r"(parity) : "memory");
}

// ---- scratch (static device globals; no allocation) ----
__device__ float g_WT[CC * DPAD];          // [c][d], zero-padded d>=100
__device__ float g_meanT[NPOS * DP];       // [n][c]
__device__ float g_proj[(size_t)BB * PIN * DP];  // [b][p][d]  (13.1 MB, fits L2)
__device__ float g_dist[(size_t)BB * NPOS];      // [b][n]

// ---------------------------------------------------------------------------
__global__ void prep_w_kernel(const float* __restrict__ W) {
    int i = blockIdx.x * blockDim.x + threadIdx.x;
    if (i < CC * DPAD) {
        int c = i / DPAD, d = i - c * DPAD;
        g_WT[i] = (d < DP) ? W[d * CC + c] : 0.f;
    }
}

// ---------------------------------------------------------------------------
__global__ void prep_mean_kernel(const float* __restrict__ mean) {
    __shared__ float t[32][33];
    const int n0 = blockIdx.x * 32, c0 = blockIdx.y * 32;
    const int tx = threadIdx.x, ty = threadIdx.y;
#pragma unroll
    for (int j = 0; j < 32; j += 8) {
        int c = c0 + ty + j;
        if (c < DP) t[ty + j][tx] = mean[(size_t)c * NPOS + n0 + tx];
    }
    __syncthreads();
    int c = c0 + tx;
    if (c < DP) {
#pragma unroll
        for (int j = 0; j < 32; j += 8) {
            int n = n0 + ty + j;
            g_meanT[(size_t)n * DP + c] = t[tx][ty + j];
        }
    }
}

// ---------------------------------------------------------------------------
// Projection at 32x32: proj[b][p][d] = sum_c X[b][c][p] * W[d][c] + bias[d]
// Grid (32 ptiles, 32 b) = 1024 blocks. 208 threads; thread = 2p x 8d.
// ---------------------------------------------------------------------------
__global__ __launch_bounds__(208) void proj_kernel(const float* __restrict__ X,
                                                   const float* __restrict__ bias) {
    __shared__ float Xs[32][32];     // [c][p]  4 KB
    __shared__ float Ws[32][DPAD];   // [c][d]  13.3 KB
    const int tid = threadIdx.x;
    const int ptile = blockIdx.x;    // 0..31 (32-p tile)
    const int b = blockIdx.y;        // 0..31
    const int pg = tid & 15;         // p base = pg*2
    const int dg = tid >> 4;         // 0..12
    const int d0 = dg * 8;
    const int p2 = pg * 2;

    unsigned long long acc[2][4];
#pragma unroll
    for (int k = 0; k < 2; k++)
#pragma unroll
        for (int q = 0; q < 4; q++) acc[k][q] = 0ull;

    const float* Xb = X + ((size_t)b * CC) * PIN + ptile * 32;

    for (int c0 = 0; c0 < CC; c0 += 32) {
        for (int i = tid; i < 32 * 32; i += 208) {
            int c = i >> 5, p = i & 31;
            Xs[c][p] = Xb[(size_t)(c0 + c) * PIN + p];
        }
        for (int i = tid; i < 32 * DPAD; i += 208) {
            int c = i / DPAD, d = i - c * DPAD;
            Ws[c][d] = g_WT[(c0 + c) * DPAD + d];
        }
        __syncthreads();

#pragma unroll 8
        for (int c = 0; c < 32; c++) {
            float2 xv = *(const float2*)&Xs[c][p2];
            ulonglong2 wa = *(const ulonglong2*)&Ws[c][d0];
            ulonglong2 wb = *(const ulonglong2*)&Ws[c][d0 + 4];
            unsigned long long xd0 = pack2(xv.x, xv.x);
            unsigned long long xd1 = pack2(xv.y, xv.y);
            acc[0][0] = fma2(xd0, wa.x, acc[0][0]);
            acc[0][1] = fma2(xd0, wa.y, acc[0][1]);
            acc[0][2] = fma2(xd0, wb.x, acc[0][2]);
            acc[0][3] = fma2(xd0, wb.y, acc[0][3]);
            acc[1][0] = fma2(xd1, wa.x, acc[1][0]);
            acc[1][1] = fma2(xd1, wa.y, acc[1][1]);
            acc[1][2] = fma2(xd1, wb.x, acc[1][2]);
            acc[1][3] = fma2(xd1, wb.y, acc[1][3]);
        }
        __syncthreads();
    }

    float4 bi0 = *(const float4*)&bias[d0];
    float4 bi1 = make_float4(0.f, 0.f, 0.f, 0.f);
    if (dg < 12) bi1 = *(const float4*)&bias[d0 + 4];
    const int pbase = ptile * 32 + p2;
#pragma unroll
    for (int k = 0; k < 2; k++) {
        float* o = g_proj + ((size_t)b * PIN + pbase + k) * DP + d0;
        float2 u0 = unpack2(acc[k][0]);
        float2 u1 = unpack2(acc[k][1]);
        *(float4*)o = make_float4(u0.x + bi0.x, u0.y + bi0.y,
                                  u1.x + bi0.z, u1.y + bi0.w);
        if (dg < 12) {
            float2 u2 = unpack2(acc[k][2]);
            float2 u3 = unpack2(acc[k][3]);
            *(float4*)(o + 4) = make_float4(u2.x + bi1.x, u2.y + bi1.y,
                                            u3.x + bi1.z, u3.y + bi1.w);
        }
    }
}

// ---------------------------------------------------------------------------
// Fused 2x bilinear upsample + mean-subtract + Mahalanobis quadratic form.
// One block per n. 256 threads. ALL 5 chunk TMAs (8 KB each, own mbarrier)
// issued eagerly at block start; compute waits per chunk, no chunk barriers.
// Dynamic smem: DmT[100][36] | IC[10000] | dists[32]
// ---------------------------------------------------------------------------
extern __shared__ float s_maha[];
__global__ __launch_bounds__(256) void maha_kernel(const float* __restrict__ ic) {
    float (*DmT)[36] = (float(*)[36])s_maha;          // 3600 floats
    float* ICs = s_maha + 3600;                       // 10000 floats
    float* dists = s_maha + 13600;                    // 32 floats
    __shared__ __align__(8) unsigned long long mbar_sto[NCHUNK];
    const int n = blockIdx.x;
    const int tid = threadIdx.x;

    unsigned int mbar0 = (unsigned int)__cvta_generic_to_shared(&mbar_sto[0]);
    unsigned int icsh = (unsigned int)__cvta_generic_to_shared(ICs);
    const float* icn = ic + (size_t)n * (DP * DP);

    if (tid == 0) {
#pragma unroll
        for (int k = 0; k < NCHUNK; k++) mbar_init(mbar0 + 8 * k, 1);
        asm volatile("fence.proxy.async.shared::cta;" ::: "memory");
#pragma unroll
        for (int k = 0; k < NCHUNK; k++) {
            mbar_expect_tx(mbar0 + 8 * k, CCHUNK * DP * 4);
            bulk_g2s(icsh + k * CCHUNK * DP * 4, icn + k * CCHUNK * DP,
                     CCHUNK * DP * 4, mbar0 + 8 * k);
        }
    }

    // bilinear source taps (half-pixel centers, clamped)
    const int yo = n >> 6, xo = n & 63;
    float yin = (yo + 0.5f) * 0.5f - 0.5f;
    float xin = (xo + 0.5f) * 0.5f - 0.5f;
    int y0 = (int)floorf(yin), x0 = (int)floorf(xin);
    float fy = yin - (float)y0, fx = xin - (float)x0;
    int y0c = max(y0, 0), y1c = min(y0 + 1, HWI - 1);
    int x0c = max(x0, 0), x1c = min(x0 + 1, HWI - 1);
    float w00 = (1.f - fy) * (1.f - fx), w01 = (1.f - fy) * fx;
    float w10 = fy * (1.f - fx),         w11 = fy * fx;
    int p00 = y0c * HWI + x0c, p01 = y0c * HWI + x1c;
    int p10 = y1c * HWI + x0c, p11 = y1c * HWI + x1c;

    // phase 1: DmT[c][b] via float4 taps (overlaps the TMA fills)
    const float* mt = g_meanT + (size_t)n * DP;
    for (int idx = tid; idx < 800; idx += 256) {
        int b = idx / 25;
        int q = idx - b * 25;
        int c = q * 4;
        const float* P = g_proj + (size_t)b * PIN * DP;
        float4 t00 = *(const float4*)&P[p00 * DP + c];
        float4 t01 = *(const float4*)&P[p01 * DP + c];
        float4 t10 = *(const float4*)&P[p10 * DP + c];
        float4 t11 = *(const float4*)&P[p11 * DP + c];
        float4 m4 = *(const float4*)&mt[c];
        DmT[c + 0][b] = w00 * t00.x + w01 * t01.x + w10 * t10.x + w11 * t11.x - m4.x;
        DmT[c + 1][b] = w00 * t00.y + w01 * t01.y + w10 * t10.y + w11 * t11.y - m4.y;
        DmT[c + 2][b] = w00 * t00.z + w01 * t01.z + w10 * t10.z + w11 * t11.z - m4.z;
        DmT[c + 3][b] = w00 * t00.w + w01 * t01.w + w10 * t10.w + w11 * t11.w - m4.w;
    }
    if (tid < BB) dists[tid] = 0.f;
    __syncthreads();

    const int bg = (tid & 7) * 4;        // batch base (0..28 step 4)
    const int d0 = (tid >> 3) * 4;       // d base (0..96)
    const bool active = tid < 200;

    unsigned long long acc[2][4];
#pragma unroll
    for (int j = 0; j < 2; j++)
#pragma unroll
        for (int q = 0; q < 4; q++) acc[j][q] = 0ull;

    for (int k = 0; k < NCHUNK; k++) {
        mbar_wait(mbar0 + 8 * k, 0);
        if (active) {
            const float* icc = ICs + k * CCHUNK * DP + d0;
#pragma unroll 5
            for (int cc = 0; cc < CCHUNK; cc++) {
                float4 icv = *(const float4*)(icc + cc * DP);
                unsigned long long icd[4];
                icd[0] = pack2(icv.x, icv.x);
                icd[1] = pack2(icv.y, icv.y);
                icd[2] = pack2(icv.z, icv.z);
                icd[3] = pack2(icv.w, icv.w);
                int c = k * CCHUNK + cc;
                ulonglong2 da = *(const ulonglong2*)&DmT[c][bg];
                unsigned long long dm[2] = {da.x, da.y};
#pragma unroll
                for (int j = 0; j < 2; j++)
#pragma unroll
                    for (int q = 0; q < 4; q++)
                        acc[j][q] = fma2(dm[j], icd[q], acc[j][q]);
            }
        }
    }

    if (active) {
#pragma unroll
        for (int j = 0; j < 2; j++) {
            unsigned long long s2 = 0ull;
#pragma unroll
            for (int q = 0; q < 4; q++) {
                unsigned long long dp =
                    *(const unsigned long long*)&DmT[d0 + q][bg + 2 * j];
                s2 = fma2(acc[j][q], dp, s2);
            }
            float2 s = unpack2(s2);
            atomicAdd(&dists[bg + 2 * j], s.x);
            atomicAdd(&dists[bg + 2 * j + 1], s.y);
        }
    }
    __syncthreads();
    if (tid < BB) g_dist[(size_t)tid * NPOS + n] = dists[tid];
}

// ---------------------------------------------------------------------------
__global__ void upsample_kernel(const float* __restrict__ nmin_p,
                                const float* __restrict__ nmax_p,
                                float* __restrict__ out) {
    const int b = blockIdx.y;
    const int i = blockIdx.x * blockDim.x + threadIdx.x;
    const int yo = i >> 6;
    const int xb = (i & 63) * 4;

    float yin = (yo + 0.5f) * 0.25f - 0.5f;
    int y0 = (int)floorf(yin);
    float fy = yin - (float)y0;
    int y0c = max(y0, 0), y1c = min(y0 + 1, HWF - 1);

    const float* dn = g_dist + (size_t)b * NPOS;
    const float* r0 = dn + y0c * HWF;
    const float* r1 = dn + y1c * HWF;
    float nmin = *nmin_p, nmax = *nmax_p;
    float inv = 1.f / (nmax - nmin + 1e-8f);

    float4 res;
    float* resp = (float*)&res;
#pragma unroll
    for (int k = 0; k < 4; k++) {
        int xo = xb + k;
        float xin = (xo + 0.5f) * 0.25f - 0.5f;
        int x0 = (int)floorf(xin);
        float fx = xin - (float)x0;
        int x0c = max(x0, 0), x1c = min(x0 + 1, HWF - 1);
        float v = (1.f - fy) * ((1.f - fx) * r0[x0c] + fx * r0[x1c])
                + fy * ((1.f - fx) * r1[x0c] + fx * r1[x1c]);
        resp[k] = (v - nmin) * inv;
    }
    *(float4*)&out[(size_t)b * (OHW * OHW) + yo * OHW + xb] = res;
}

// ---------------------------------------------------------------------------
extern "C" void kernel_launch(void* const* d_in, const int* in_sizes, int n_in,
                              void* d_out, int out_size) {
    (void)in_sizes; (void)n_in; (void)out_size;
    const float* combined = (const float*)d_in[0];
    const float* proj_w   = (const float*)d_in[1];
    const float* proj_b   = (const float*)d_in[2];
    const float* mean     = (const float*)d_in[3];
    const float* inv_cov  = (const float*)d_in[4];
    const float* nmin     = (const float*)d_in[5];
    const float* nmax     = (const float*)d_in[6];
    float* out = (float*)d_out;

    static int smem_set = 0;
    if (!smem_set) {
        cudaFuncSetAttribute(maha_kernel,
                             cudaFuncAttributeMaxDynamicSharedMemorySize,
                             13632 * 4);
        smem_set = 1;
    }

    prep_w_kernel<<<(CC * DPAD + 255) / 256, 256>>>(proj_w);
    prep_mean_kernel<<<dim3(NPOS / 32, 4), dim3(32, 8)>>>(mean);
    proj_kernel<<<dim3(32, BB), 208>>>(combined, proj_b);
    maha_kernel<<<NPOS, 256, 13632 * 4>>>(inv_cov);
    upsample_kernel<<<dim3(OHW * OHW / (256 * 4), BB), 256>>>(nmin, nmax, out);
}

// round 11
// speedup vs baseline: 1.2612x; 1.2612x over previous
#include <cuda_runtime.h>
#include <cstdint>

#define BB 32
#define CC 448
#define HWI 32
#define PIN 1024       // 32*32
#define HWF 64
#define NPOS 4096
#define DP 100
#define DPAD 104
#define OHW 256

// ---- packed f32x2 helpers (sm_103a) ----
__device__ __forceinline__ unsigned long long pack2(float lo, float hi) {
    unsigned long long r;
    asm("mov.b64 %0, {%1, %2};" : "=l"(r) : "f"(lo), "f"(hi));
    return r;
}
__device__ __forceinline__ float2 unpack2(unsigned long long v) {
    float lo, hi;
    asm("mov.b64 {%0, %1}, %2;" : "=f"(lo), "=f"(hi) : "l"(v));
    return make_float2(lo, hi);
}
__device__ __forceinline__ unsigned long long fma2(unsigned long long a,
                                                   unsigned long long b,
                                                   unsigned long long c) {
    unsigned long long d;
    asm("fma.rn.f32x2 %0, %1, %2, %3;" : "=l"(d) : "l"(a), "l"(b), "l"(c));
    return d;
}
__device__ __forceinline__ void mbar_init(unsigned int mbar, unsigned int cnt) {
    asm volatile("mbarrier.init.shared.b64 [%0], %1;" :: "r"(mbar), "r"(cnt) : "memory");
}
__device__ __forceinline__ void mbar_expect_tx(unsigned int mbar, unsigned int bytes) {
    asm volatile("mbarrier.arrive.expect_tx.shared.b64 _, [%0], %1;"
                 :: "r"(mbar), "r"(bytes) : "memory");
}
__device__ __forceinline__ void bulk_g2s(unsigned int sdst, const void* gsrc,
                                         unsigned int bytes, unsigned int mbar) {
    asm volatile("cp.async.bulk.shared::cta.global.mbarrier::complete_tx::bytes "
                 "[%0], [%1], %2, [%3];"
                 :: "r"(sdst), "l"(gsrc), "r"(bytes), "r"(mbar) : "memory");
}
__device__ __forceinline__ void mbar_wait(unsigned int mbar, unsigned int parity) {
    asm volatile(
        "{\n\t.reg .pred P;\n\t"
        "WAIT_%=:\n\t"
        "mbarrier.try_wait.parity.acquire.cta.shared::cta.b64 P, [%0], %1, 0x989680;\n\t"
        "@P bra.uni DONE_%=;\n\t"
        "bra.uni WAIT_%=;\n\t"
        "DONE_%=:\n\t}"
        :: "r"(mbar), "r"(parity) : "memory");
}

// m16n8k8 tf32 MMA (A row-major, B col-major), accumulate in place.
__device__ __forceinline__ void mma8(float* d, const unsigned* a, const unsigned* b) {
    asm volatile(
        "mma.sync.aligned.m16n8k8.row.col.f32.tf32.tf32.f32 "
        "{%0,%1,%2,%3}, {%4,%5,%6,%7}, {%8,%9}, {%0,%1,%2,%3};"
        : "+f"(d[0]), "+f"(d[1]), "+f"(d[2]), "+f"(d[3])
        : "r"(a[0]), "r"(a[1]), "r"(a[2]), "r"(a[3]), "r"(b[0]), "r"(b[1]));
}

// ---- scratch (static device globals; no allocation) ----
__device__ float g_WT[CC * DPAD];
__device__ float g_meanT[NPOS * DP];
__device__ float g_proj[(size_t)BB * PIN * DP];
__device__ float g_dist[(size_t)BB * NPOS];

// ---------------------------------------------------------------------------
__global__ void prep_w_kernel(const float* __restrict__ W) {
    int i = blockIdx.x * blockDim.x + threadIdx.x;
    if (i < CC * DPAD) {
        int c = i / DPAD, d = i - c * DPAD;
        g_WT[i] = (d < DP) ? W[d * CC + c] : 0.f;
    }
}

// ---------------------------------------------------------------------------
__global__ void prep_mean_kernel(const float* __restrict__ mean) {
    __shared__ float t[32][33];
    const int n0 = blockIdx.x * 32, c0 = blockIdx.y * 32;
    const int tx = threadIdx.x, ty = threadIdx.y;
#pragma unroll
    for (int j = 0; j < 32; j += 8) {
        int c = c0 + ty + j;
        if (c < DP) t[ty + j][tx] = mean[(size_t)c * NPOS + n0 + tx];
    }
    __syncthreads();
    int c = c0 + tx;
    if (c < DP) {
#pragma unroll
        for (int j = 0; j < 32; j += 8) {
            int n = n0 + ty + j;
            g_meanT[(size_t)n * DP + c] = t[tx][ty + j];
        }
    }
}

// ---------------------------------------------------------------------------
// Projection (R6-proven): 208 threads, thread = 4p x 8d, grid (16, 32).
// ---------------------------------------------------------------------------
__global__ __launch_bounds__(208) void proj_kernel(const float* __restrict__ X,
                                                   const float* __restrict__ bias) {
    __shared__ float Xs[32][64];
    __shared__ float Ws[32][DPAD];
    const int tid = threadIdx.x;
    const int ptile = blockIdx.x;
    const int b = blockIdx.y;
    const int pg = tid & 15;
    const int dg = tid >> 4;
    const int d0 = dg * 8;

    unsigned long long acc[4][4];
#pragma unroll
    for (int k = 0; k < 4; k++)
#pragma unroll
        for (int q = 0; q < 4; q++) acc[k][q] = 0ull;

    const float* Xb = X + ((size_t)b * CC) * PIN + ptile * 64;

    for (int c0 = 0; c0 < CC; c0 += 32) {
        for (int i = tid; i < 32 * 64; i += 208) {
            int c = i >> 6, p = i & 63;
            Xs[c][p] = Xb[(size_t)(c0 + c) * PIN + p];
        }
        for (int i = tid; i < 32 * DPAD; i += 208) {
            int c = i / DPAD, d = i - c * DPAD;
            Ws[c][d] = g_WT[(c0 + c) * DPAD + d];
        }
        __syncthreads();

#pragma unroll 4
        for (int c = 0; c < 32; c++) {
            float4 x0 = *(const float4*)&Xs[c][pg * 4];
            ulonglong2 wa = *(const ulonglong2*)&Ws[c][d0];
            ulonglong2 wb = *(const ulonglong2*)&Ws[c][d0 + 4];
            unsigned long long wp[4] = {wa.x, wa.y, wb.x, wb.y};
            float xv[4] = {x0.x, x0.y, x0.z, x0.w};
            unsigned long long xd[4];
#pragma unroll
            for (int k = 0; k < 4; k++) xd[k] = pack2(xv[k], xv[k]);
#pragma unroll
            for (int k = 0; k < 4; k++)
#pragma unroll
                for (int q = 0; q < 4; q++)
                    acc[k][q] = fma2(xd[k], wp[q], acc[k][q]);
        }
        __syncthreads();
    }

    float4 bi0 = *(const float4*)&bias[d0];
    float4 bi1 = make_float4(0.f, 0.f, 0.f, 0.f);
    if (dg < 12) bi1 = *(const float4*)&bias[d0 + 4];
    const int pbase = ptile * 64 + pg * 4;
#pragma unroll
    for (int k = 0; k < 4; k++) {
        float* o = g_proj + ((size_t)b * PIN + pbase + k) * DP + d0;
        float2 u0 = unpack2(acc[k][0]);
        float2 u1 = unpack2(acc[k][1]);
        *(float4*)o = make_float4(u0.x + bi0.x, u0.y + bi0.y,
                                  u1.x + bi0.z, u1.y + bi0.w);
        if (dg < 12) {
            float2 u2 = unpack2(acc[k][2]);
            float2 u3 = unpack2(acc[k][3]);
            *(float4*)(o + 4) = make_float4(u2.x + bi1.x, u2.y + bi1.y,
                                            u3.x + bi1.z, u3.y + bi1.w);
        }
    }
}

// ---------------------------------------------------------------------------
// Tensor-core Mahalanobis via mma.sync m16n8k8 tf32. One block per n, 128 thr.
// D[b][j] = sum_k diff[b,k]*IC[j,k];  dist[b] = sum_j D[b,j]*diff[b,j]
// diff: rna-tf32 in smem DmT[k][b] (stride 40 -> conflict-free frags).
// IC: raw fp32 smem [104][100] (rows 100-103 zeroed); split tf32 hi/lo in regs.
// 13 j-tiles over 4 warps; per jt: 13 k-steps x 2 m-tiles x (hi,lo) MMAs.
// Dyn smem floats: ICs[0..10400) | DmT[10400..14560)   (58240 B)
// ---------------------------------------------------------------------------
extern __shared__ float s_mh[];
__global__ __launch_bounds__(128) void maha_kernel(const float* __restrict__ ic) {
    float* ICs = s_mh;                 // [104][100]
    float* DmT = s_mh + 10400;         // [104][40] (cols 0..31 used)
    __shared__ float dists[BB];
    __shared__ __align__(8) unsigned long long mbar_sto[5];

    const int n = blockIdx.x;
    const int tid = threadIdx.x;
    const int w = tid >> 5, lane = tid & 31;
    const int g = lane >> 2, tig = lane & 3;

    unsigned int mb0 = (unsigned int)__cvta_generic_to_shared(&mbar_sto[0]);
    unsigned int icsh = (unsigned int)__cvta_generic_to_shared(ICs);
    const float* icn = ic + (size_t)n * (DP * DP);

    if (tid == 0) {
#pragma unroll
        for (int k = 0; k < 5; k++) mbar_init(mb0 + 8 * k, 1);
        asm volatile("fence.proxy.async.shared::cta;" ::: "memory");
#pragma unroll
        for (int k = 0; k < 5; k++) {
            mbar_expect_tx(mb0 + 8 * k, 8000);
            bulk_g2s(icsh + k * 8000, icn + k * 2000, 8000, mb0 + 8 * k);
        }
    }

    // zero padding: ICs rows 100-103 (400 floats), DmT rows 100-103 cols 0-31
    for (int i = tid; i < 400; i += 128) ICs[10000 + i] = 0.f;
    DmT[(100 + (tid >> 5)) * 40 + (tid & 31)] = 0.f;
    if (tid < BB) dists[tid] = 0.f;

    // ---- phase 1: diff -> DmT (rna-tf32 values stored as f32) ----
    const int yo = n >> 6, xo = n & 63;
    float yin = (yo + 0.5f) * 0.5f - 0.5f;
    float xin = (xo + 0.5f) * 0.5f - 0.5f;
    int y0 = (int)floorf(yin), x0 = (int)floorf(xin);
    float fy = yin - (float)y0, fx = xin - (float)x0;
    int y0c = max(y0, 0), y1c = min(y0 + 1, HWI - 1);
    int x0c = max(x0, 0), x1c = min(x0 + 1, HWI - 1);
    float w00 = (1.f - fy) * (1.f - fx), w01 = (1.f - fy) * fx;
    float w10 = fy * (1.f - fx),         w11 = fy * fx;
    int p00 = y0c * HWI + x0c, p01 = y0c * HWI + x1c;
    int p10 = y1c * HWI + x0c, p11 = y1c * HWI + x1c;

    const float* mt = g_meanT + (size_t)n * DP;
    for (int idx = tid; idx < 800; idx += 128) {
        int b = idx / 25;
        int q = idx - b * 25;
        int c = q * 4;
        const float* P = g_proj + (size_t)b * PIN * DP;
        float4 t00 = *(const float4*)&P[p00 * DP + c];
        float4 t01 = *(const float4*)&P[p01 * DP + c];
        float4 t10 = *(const float4*)&P[p10 * DP + c];
        float4 t11 = *(const float4*)&P[p11 * DP + c];
        float4 m4 = *(const float4*)&mt[c];
        float v0 = w00 * t00.x + w01 * t01.x + w10 * t10.x + w11 * t11.x - m4.x;
        float v1 = w00 * t00.y + w01 * t01.y + w10 * t10.y + w11 * t11.y - m4.y;
        float v2 = w00 * t00.z + w01 * t01.z + w10 * t10.z + w11 * t11.z - m4.z;
        float v3 = w00 * t00.w + w01 * t01.w + w10 * t10.w + w11 * t11.w - m4.w;
        unsigned r0, r1, r2, r3;
        asm("cvt.rna.tf32.f32 %0, %1;" : "=r"(r0) : "f"(v0));
        asm("cvt.rna.tf32.f32 %0, %1;" : "=r"(r1) : "f"(v1));
        asm("cvt.rna.tf32.f32 %0, %1;" : "=r"(r2) : "f"(v2));
        asm("cvt.rna.tf32.f32 %0, %1;" : "=r"(r3) : "f"(v3));
        DmT[(c + 0) * 40 + b] = __uint_as_float(r0);
        DmT[(c + 1) * 40 + b] = __uint_as_float(r1);
        DmT[(c + 2) * 40 + b] = __uint_as_float(r2);
        DmT[(c + 3) * 40 + b] = __uint_as_float(r3);
    }
    __syncthreads();

    // ---- main: each warp owns j-tiles w, w+4, w+8 (+12 for w==0) ----
    float accd[4] = {0.f, 0.f, 0.f, 0.f};   // dist partials: b = g, g+8, 16+g, 24+g... (m0, row)
    int waited = -1;

    for (int t = w; t < 13; t += 4) {
        int need = (8 * t + 7) / 20;
        if (need > 4) need = 4;
        while (waited < need) { waited++; mbar_wait(mb0 + 8 * waited, 0); }
        const int j0 = 8 * t;

        float d0[4] = {0.f, 0.f, 0.f, 0.f};   // m-tile 0 (b 0..15)
        float d1[4] = {0.f, 0.f, 0.f, 0.f};   // m-tile 1 (b 16..31)
#pragma unroll
        for (int s = 0; s < 13; s++) {
            const int k0 = 8 * s;
            float braw0 = ICs[(j0 + g) * DP + k0 + tig];
            float braw1 = (s < 12) ? ICs[(j0 + g) * DP + k0 + tig + 4] : 0.f;
            unsigned bh[2], bl[2];
            bh[0] = __float_as_uint(braw0) & 0xFFFFE000u;
            bh[1] = __float_as_uint(braw1) & 0xFFFFE000u;
            bl[0] = __float_as_uint(braw0 - __uint_as_float(bh[0]));
            bl[1] = __float_as_uint(braw1 - __uint_as_float(bh[1]));
            unsigned a0[4], a1[4];
            a0[0] = __float_as_uint(DmT[(k0 + tig) * 40 + g]);
            a0[1] = __float_as_uint(DmT[(k0 + tig) * 40 + g + 8]);
            a0[2] = __float_as_uint(DmT[(k0 + tig + 4) * 40 + g]);
            a0[3] = __float_as_uint(DmT[(k0 + tig + 4) * 40 + g + 8]);
            a1[0] = __float_as_uint(DmT[(k0 + tig) * 40 + 16 + g]);
            a1[1] = __float_as_uint(DmT[(k0 + tig) * 40 + 24 + g]);
            a1[2] = __float_as_uint(DmT[(k0 + tig + 4) * 40 + 16 + g]);
            a1[3] = __float_as_uint(DmT[(k0 + tig + 4) * 40 + 24 + g]);
            mma8(d0, a0, bh);
            mma8(d0, a0, bl);
            mma8(d1, a1, bh);
            mma8(d1, a1, bl);
        }
        // fold this j-tile into dist partials: cols j0+2*tig, j0+2*tig+1
        const float* wj0 = &DmT[(j0 + 2 * tig) * 40];
        const float* wj1 = &DmT[(j0 + 2 * tig + 1) * 40];
        accd[0] += d0[0] * wj0[g]      + d0[1] * wj1[g];
        accd[1] += d0[2] * wj0[g + 8]  + d0[3] * wj1[g + 8];
        accd[2] += d1[0] * wj0[16 + g] + d1[1] * wj1[16 + g];
        accd[3] += d1[2] * wj0[24 + g] + d1[3] * wj1[24 + g];
    }

    atomicAdd(&dists[g], accd[0]);
    atomicAdd(&dists[g + 8], accd[1]);
    atomicAdd(&dists[16 + g], accd[2]);
    atomicAdd(&dists[24 + g], accd[3]);
    __syncthreads();
    if (tid < BB) g_dist[(size_t)tid * NPOS + n] = dists[tid];
}

// ---------------------------------------------------------------------------
__global__ void upsample_kernel(const float* __restrict__ nmin_p,
                                const float* __restrict__ nmax_p,
                                float* __restrict__ out) {
    const int b = blockIdx.y;
    const int i = blockIdx.x * blockDim.x + threadIdx.x;
    const int yo = i >> 6;
    const int xb = (i & 63) * 4;

    float yin = (yo + 0.5f) * 0.25f - 0.5f;
    int y0 = (int)floorf(yin);
    float fy = yin - (float)y0;
    int y0c = max(y0, 0), y1c = min(y0 + 1, HWF - 1);

    const float* dn = g_dist + (size_t)b * NPOS;
    const float* r0 = dn + y0c * HWF;
    const float* r1 = dn + y1c * HWF;
    float nmin = *nmin_p, nmax = *nmax_p;
    float inv = 1.f / (nmax - nmin + 1e-8f);

    float4 res;
    float* resp = (float*)&res;
#pragma unroll
    for (int k = 0; k < 4; k++) {
        int xo = xb + k;
        float xin = (xo + 0.5f) * 0.25f - 0.5f;
        int x0 = (int)floorf(xin);
        float fx = xin - (float)x0;
        int x0c = max(x0, 0), x1c = min(x0 + 1, HWF - 1);
        float v = (1.f - fy) * ((1.f - fx) * r0[x0c] + fx * r0[x1c])
                + fy * ((1.f - fx) * r1[x0c] + fx * r1[x1c]);
        resp[k] = (v - nmin) * inv;
    }
    *(float4*)&out[(size_t)b * (OHW * OHW) + yo * OHW + xb] = res;
}

// ---------------------------------------------------------------------------
extern "C" void kernel_launch(void* const* d_in, const int* in_sizes, int n_in,
                              void* d_out, int out_size) {
    (void)in_sizes; (void)n_in; (void)out_size;
    const float* combined = (const float*)d_in[0];
    const float* proj_w   = (const float*)d_in[1];
    const float* proj_b   = (const float*)d_in[2];
    const float* mean     = (const float*)d_in[3];
    const float* inv_cov  = (const float*)d_in[4];
    const float* nmin     = (const float*)d_in[5];
    const float* nmax     = (const float*)d_in[6];
    float* out = (float*)d_out;

    static int smem_set = 0;
    if (!smem_set) {
        cudaFuncSetAttribute(maha_kernel,
                             cudaFuncAttributeMaxDynamicSharedMemorySize,
                             58240);
        smem_set = 1;
    }

    prep_w_kernel<<<(CC * DPAD + 255) / 256, 256>>>(proj_w);
    prep_mean_kernel<<<dim3(NPOS / 32, 4), dim3(32, 8)>>>(mean);
    proj_kernel<<<dim3(16, BB), 208>>>(combined, proj_b);
    maha_kernel<<<NPOS, 128, 58240>>>(inv_cov);
    upsample_kernel<<<dim3(OHW * OHW / (256 * 4), BB), 256>>>(nmin, nmax, out);
}

// round 12
// speedup vs baseline: 1.3706x; 1.0867x over previous
#include <cuda_runtime.h>
#include <cstdint>

#define BB 32
#define CC 448
#define HWI 32
#define PIN 1024       // 32*32
#define HWF 64
#define NPOS 4096
#define DP 100
#define DPAD 104
#define OHW 256

__device__ __forceinline__ void mbar_init(unsigned int mbar, unsigned int cnt) {
    asm volatile("mbarrier.init.shared.b64 [%0], %1;" :: "r"(mbar), "r"(cnt) : "memory");
}
__device__ __forceinline__ void mbar_expect_tx(unsigned int mbar, unsigned int bytes) {
    asm volatile("mbarrier.arrive.expect_tx.shared.b64 _, [%0], %1;"
                 :: "r"(mbar), "r"(bytes) : "memory");
}
__device__ __forceinline__ void bulk_g2s(unsigned int sdst, const void* gsrc,
                                         unsigned int bytes, unsigned int mbar) {
    asm volatile("cp.async.bulk.shared::cta.global.mbarrier::complete_tx::bytes "
                 "[%0], [%1], %2, [%3];"
                 :: "r"(sdst), "l"(gsrc), "r"(bytes), "r"(mbar) : "memory");
}
__device__ __forceinline__ void mbar_wait(unsigned int mbar, unsigned int parity) {
    asm volatile(
        "{\n\t.reg .pred P;\n\t"
        "WAIT_%=:\n\t"
        "mbarrier.try_wait.parity.acquire.cta.shared::cta.b64 P, [%0], %1, 0x989680;\n\t"
        "@P bra.uni DONE_%=;\n\t"
        "bra.uni WAIT_%=;\n\t"
        "DONE_%=:\n\t}"
        :: "r"(mbar), "r"(parity) : "memory");
}

// m16n8k8 tf32 MMA (A row-major, B col-major), accumulate in place.
__device__ __forceinline__ void mma8(float* d, const unsigned* a, const unsigned* b) {
    asm volatile(
        "mma.sync.aligned.m16n8k8.row.col.f32.tf32.tf32.f32 "
        "{%0,%1,%2,%3}, {%4,%5,%6,%7}, {%8,%9}, {%0,%1,%2,%3};"
        : "+f"(d[0]), "+f"(d[1]), "+f"(d[2]), "+f"(d[3])
        : "r"(a[0]), "r"(a[1]), "r"(a[2]), "r"(a[3]), "r"(b[0]), "r"(b[1]));
}

// ---- scratch (static device globals; no allocation) ----
__device__ float g_Whi[DPAD * CC];   // [d][c] tf32-hi, rows 100..103 zero
__device__ float g_Wlo[DPAD * CC];   // [d][c] residual
__device__ float g_meanT[NPOS * DP];
__device__ float g_proj[(size_t)BB * PIN * DP];
__device__ float g_dist[(size_t)BB * NPOS];

// ---------------------------------------------------------------------------
// prep_w: split W[100][448] into exact tf32 hi/lo planes, zero-pad d to 104.
// ---------------------------------------------------------------------------
__global__ void prep_w_kernel(const float* __restrict__ W) {
    int i = blockIdx.x * blockDim.x + threadIdx.x;
    if (i < DPAD * CC) {
        int d = i / CC;
        float v = (d < DP) ? W[i] : 0.f;
        float hi = __uint_as_float(__float_as_uint(v) & 0xFFFFE000u);
        g_Whi[i] = hi;
        g_Wlo[i] = v - hi;
    }
}

// ---------------------------------------------------------------------------
__global__ void prep_mean_kernel(const float* __restrict__ mean) {
    __shared__ float t[32][33];
    const int n0 = blockIdx.x * 32, c0 = blockIdx.y * 32;
    const int tx = threadIdx.x, ty = threadIdx.y;
#pragma unroll
    for (int j = 0; j < 32; j += 8) {
        int c = c0 + ty + j;
        if (c < DP) t[ty + j][tx] = mean[(size_t)c * NPOS + n0 + tx];
    }
    __syncthreads();
    int c = c0 + tx;
    if (c < DP) {
#pragma unroll
        for (int j = 0; j < 32; j += 8) {
            int n = n0 + ty + j;
            g_meanT[(size_t)n * DP + c] = t[tx][ty + j];
        }
    }
}

// ---------------------------------------------------------------------------
// Tensor-core projection: proj[b][p][d] = sum_c X[b][c][p] * W[d][c] + bias[d]
// Grid (16 ptiles, 32 b), 128 threads = 4 warps; warp w owns m-tile p = w*16.
// A = X^T (rows p, k=c) from Xs[c][p] (pad 72 -> conflict-free frag loads).
// B = W (rows d, k=c) hi/lo from smem (pad 36 -> conflict-free).
// 3-term split: Ah*Bh + Al*Bh + Ah*Bl  (error ~2^-21).
// ---------------------------------------------------------------------------
__global__ __launch_bounds__(128) void proj_kernel(const float* __restrict__ X,
                                                   const float* __restrict__ bias) {
    __shared__ float Xs[32 * 72];        // [c][p] 9.2 KB
    __shared__ float Wh[DPAD * 36];      // [d][k] 15 KB
    __shared__ float Wl[DPAD * 36];      // 15 KB
    const int tid = threadIdx.x;
    const int w = tid >> 5, lane = tid & 31;
    const int g = lane >> 2, tig = lane & 3;
    const int ptile = blockIdx.x;
    const int b = blockIdx.y;
    const int ploc = w * 16;             // local m-tile base

    float D[13][4];
#pragma unroll
    for (int n = 0; n < 13; n++)
#pragma unroll
        for (int q = 0; q < 4; q++) D[n][q] = 0.f;

    const float* Xb = X + ((size_t)b * CC) * PIN + ptile * 64;

    for (int c0 = 0; c0 < CC; c0 += 32) {
        for (int i = tid; i < 2048; i += 128) {
            int c = i >> 6, p = i & 63;
            Xs[c * 72 + p] = Xb[(size_t)(c0 + c) * PIN + p];
        }
        for (int i = tid; i < DPAD * 32; i += 128) {
            int d = i >> 5, k = i & 31;
            Wh[d * 36 + k] = g_Whi[d * CC + c0 + k];
            Wl[d * 36 + k] = g_Wlo[d * CC + c0 + k];
        }
        __syncthreads();

#pragma unroll
        for (int s = 0; s < 4; s++) {
            const int k0 = 8 * s;
            float ra[4];
            ra[0] = Xs[(k0 + tig) * 72 + ploc + g];
            ra[1] = Xs[(k0 + tig) * 72 + ploc + g + 8];
            ra[2] = Xs[(k0 + tig + 4) * 72 + ploc + g];
            ra[3] = Xs[(k0 + tig + 4) * 72 + ploc + g + 8];
            unsigned ah[4], al[4];
#pragma unroll
            for (int q = 0; q < 4; q++) {
                ah[q] = __float_as_uint(ra[q]) & 0xFFFFE000u;
                al[q] = __float_as_uint(ra[q] - __uint_as_float(ah[q]));
            }
#pragma unroll
            for (int n = 0; n < 13; n++) {
                const int dr = (8 * n + g) * 36 + k0 + tig;
                unsigned bh[2], bl[2];
                bh[0] = __float_as_uint(Wh[dr]);
                bh[1] = __float_as_uint(Wh[dr + 4]);
                bl[0] = __float_as_uint(Wl[dr]);
                bl[1] = __float_as_uint(Wl[dr + 4]);
                mma8(D[n], ah, bh);
                mma8(D[n], al, bh);
                mma8(D[n], ah, bl);
            }
        }
        __syncthreads();
    }

    // epilogue: bias + store. Thread holds cols 8n+2tig, +1; rows p+g, p+g+8.
    const int prow = ptile * 64 + ploc + g;
#pragma unroll
    for (int n = 0; n < 13; n++) {
        const int db = 8 * n + 2 * tig;
        if (db < DP) {
            float b0 = bias[db], b1 = bias[db + 1];
            float* o0 = g_proj + ((size_t)b * PIN + prow) * DP + db;
            float* o1 = g_proj + ((size_t)b * PIN + prow + 8) * DP + db;
            *(float2*)o0 = make_float2(D[n][0] + b0, D[n][1] + b1);
            *(float2*)o1 = make_float2(D[n][2] + b0, D[n][3] + b1);
        }
    }
}

// ---------------------------------------------------------------------------
// Tensor-core Mahalanobis (R11-proven). One block per n, 128 thr.
// ---------------------------------------------------------------------------
extern __shared__ float s_mh[];
__global__ __launch_bounds__(128) void maha_kernel(const float* __restrict__ ic) {
    float* ICs = s_mh;                 // [104][100]
    float* DmT = s_mh + 10400;         // [104][40] (cols 0..31 used)
    __shared__ float dists[BB];
    __shared__ __align__(8) unsigned long long mbar_sto[5];

    const int n = blockIdx.x;
    const int tid = threadIdx.x;
    const int w = tid >> 5, lane = tid & 31;
    const int g = lane >> 2, tig = lane & 3;

    unsigned int mb0 = (unsigned int)__cvta_generic_to_shared(&mbar_sto[0]);
    unsigned int icsh = (unsigned int)__cvta_generic_to_shared(ICs);
    const float* icn = ic + (size_t)n * (DP * DP);

    if (tid == 0) {
#pragma unroll
        for (int k = 0; k < 5; k++) mbar_init(mb0 + 8 * k, 1);
        asm volatile("fence.proxy.async.shared::cta;" ::: "memory");
#pragma unroll
        for (int k = 0; k < 5; k++) {
            mbar_expect_tx(mb0 + 8 * k, 8000);
            bulk_g2s(icsh + k * 8000, icn + k * 2000, 8000, mb0 + 8 * k);
        }
    }

    for (int i = tid; i < 400; i += 128) ICs[10000 + i] = 0.f;
    DmT[(100 + (tid >> 5)) * 40 + (tid & 31)] = 0.f;
    if (tid < BB) dists[tid] = 0.f;

    const int yo = n >> 6, xo = n & 63;
    float yin = (yo + 0.5f) * 0.5f - 0.5f;
    float xin = (xo + 0.5f) * 0.5f - 0.5f;
    int y0 = (int)floorf(yin), x0 = (int)floorf(xin);
    float fy = yin - (float)y0, fx = xin - (float)x0;
    int y0c = max(y0, 0), y1c = min(y0 + 1, HWI - 1);
    int x0c = max(x0, 0), x1c = min(x0 + 1, HWI - 1);
    float w00 = (1.f - fy) * (1.f - fx), w01 = (1.f - fy) * fx;
    float w10 = fy * (1.f - fx),         w11 = fy * fx;
    int p00 = y0c * HWI + x0c, p01 = y0c * HWI + x1c;
    int p10 = y1c * HWI + x0c, p11 = y1c * HWI + x1c;

    const float* mt = g_meanT + (size_t)n * DP;
    for (int idx = tid; idx < 800; idx += 128) {
        int b = idx / 25;
        int q = idx - b * 25;
        int c = q * 4;
        const float* P = g_proj + (size_t)b * PIN * DP;
        float4 t00 = *(const float4*)&P[p00 * DP + c];
        float4 t01 = *(const float4*)&P[p01 * DP + c];
        float4 t10 = *(const float4*)&P[p10 * DP + c];
        float4 t11 = *(const float4*)&P[p11 * DP + c];
        float4 m4 = *(const float4*)&mt[c];
        float v0 = w00 * t00.x + w01 * t01.x + w10 * t10.x + w11 * t11.x - m4.x;
        float v1 = w00 * t00.y + w01 * t01.y + w10 * t10.y + w11 * t11.y - m4.y;
        float v2 = w00 * t00.z + w01 * t01.z + w10 * t10.z + w11 * t11.z - m4.z;
        float v3 = w00 * t00.w + w01 * t01.w + w10 * t10.w + w11 * t11.w - m4.w;
        unsigned r0, r1, r2, r3;
        asm("cvt.rna.tf32.f32 %0, %1;" : "=r"(r0) : "f"(v0));
        asm("cvt.rna.tf32.f32 %0, %1;" : "=r"(r1) : "f"(v1));
        asm("cvt.rna.tf32.f32 %0, %1;" : "=r"(r2) : "f"(v2));
        asm("cvt.rna.tf32.f32 %0, %1;" : "=r"(r3) : "f"(v3));
        DmT[(c + 0) * 40 + b] = __uint_as_float(r0);
        DmT[(c + 1) * 40 + b] = __uint_as_float(r1);
        DmT[(c + 2) * 40 + b] = __uint_as_float(r2);
        DmT[(c + 3) * 40 + b] = __uint_as_float(r3);
    }
    __syncthreads();

    float accd[4] = {0.f, 0.f, 0.f, 0.f};
    int waited = -1;

    for (int t = w; t < 13; t += 4) {
        int need = (8 * t + 7) / 20;
        if (need > 4) need = 4;
        while (waited < need) { waited++; mbar_wait(mb0 + 8 * waited, 0); }
        const int j0 = 8 * t;

        float d0[4] = {0.f, 0.f, 0.f, 0.f};
        float d1[4] = {0.f, 0.f, 0.f, 0.f};
#pragma unroll
        for (int s = 0; s < 13; s++) {
            const int k0 = 8 * s;
            float braw0 = ICs[(j0 + g) * DP + k0 + tig];
            float braw1 = (s < 12) ? ICs[(j0 + g) * DP + k0 + tig + 4] : 0.f;
            unsigned bh[2], bl[2];
            bh[0] = __float_as_uint(braw0) & 0xFFFFE000u;
            bh[1] = __float_as_uint(braw1) & 0xFFFFE000u;
            bl[0] = __float_as_uint(braw0 - __uint_as_float(bh[0]));
            bl[1] = __float_as_uint(braw1 - __uint_as_float(bh[1]));
            unsigned a0[4], a1[4];
            a0[0] = __float_as_uint(DmT[(k0 + tig) * 40 + g]);
            a0[1] = __float_as_uint(DmT[(k0 + tig) * 40 + g + 8]);
            a0[2] = __float_as_uint(DmT[(k0 + tig + 4) * 40 + g]);
            a0[3] = __float_as_uint(DmT[(k0 + tig + 4) * 40 + g + 8]);
            a1[0] = __float_as_uint(DmT[(k0 + tig) * 40 + 16 + g]);
            a1[1] = __float_as_uint(DmT[(k0 + tig) * 40 + 24 + g]);
            a1[2] = __float_as_uint(DmT[(k0 + tig + 4) * 40 + 16 + g]);
            a1[3] = __float_as_uint(DmT[(k0 + tig + 4) * 40 + 24 + g]);
            mma8(d0, a0, bh);
            mma8(d0, a0, bl);
            mma8(d1, a1, bh);
            mma8(d1, a1, bl);
        }
        const float* wj0 = &DmT[(j0 + 2 * tig) * 40];
        const float* wj1 = &DmT[(j0 + 2 * tig + 1) * 40];
        accd[0] += d0[0] * wj0[g]      + d0[1] * wj1[g];
        accd[1] += d0[2] * wj0[g + 8]  + d0[3] * wj1[g + 8];
        accd[2] += d1[0] * wj0[16 + g] + d1[1] * wj1[16 + g];
        accd[3] += d1[2] * wj0[24 + g] + d1[3] * wj1[24 + g];
    }

    atomicAdd(&dists[g], accd[0]);
    atomicAdd(&dists[g + 8], accd[1]);
    atomicAdd(&dists[16 + g], accd[2]);
    atomicAdd(&dists[24 + g], accd[3]);
    __syncthreads();
    if (tid < BB) g_dist[(size_t)tid * NPOS + n] = dists[tid];
}

// ---------------------------------------------------------------------------
__global__ void upsample_kernel(const float* __restrict__ nmin_p,
                                const float* __restrict__ nmax_p,
                                float* __restrict__ out) {
    const int b = blockIdx.y;
    const int i = blockIdx.x * blockDim.x + threadIdx.x;
    const int yo = i >> 6;
    const int xb = (i & 63) * 4;

    float yin = (yo + 0.5f) * 0.25f - 0.5f;
    int y0 = (int)floorf(yin);
    float fy = yin - (float)y0;
    int y0c = max(y0, 0), y1c = min(y0 + 1, HWF - 1);

    const float* dn = g_dist + (size_t)b * NPOS;
    const float* r0 = dn + y0c * HWF;
    const float* r1 = dn + y1c * HWF;
    float nmin = *nmin_p, nmax = *nmax_p;
    float inv = 1.f / (nmax - nmin + 1e-8f);

    float4 res;
    float* resp = (float*)&res;
#pragma unroll
    for (int k = 0; k < 4; k++) {
        int xo = xb + k;
        float xin = (xo + 0.5f) * 0.25f - 0.5f;
        int x0 = (int)floorf(xin);
        float fx = xin - (float)x0;
        int x0c = max(x0, 0), x1c = min(x0 + 1, HWF - 1);
        float v = (1.f - fy) * ((1.f - fx) * r0[x0c] + fx * r0[x1c])
                + fy * ((1.f - fx) * r1[x0c] + fx * r1[x1c]);
        resp[k] = (v - nmin) * inv;
    }
    *(float4*)&out[(size_t)b * (OHW * OHW) + yo * OHW + xb] = res;
}

// ---------------------------------------------------------------------------
extern "C" void kernel_launch(void* const* d_in, const int* in_sizes, int n_in,
                              void* d_out, int out_size) {
    (void)in_sizes; (void)n_in; (void)out_size;
    const float* combined = (const float*)d_in[0];
    const float* proj_w   = (const float*)d_in[1];
    const float* proj_b   = (const float*)d_in[2];
    const float* mean     = (const float*)d_in[3];
    const float* inv_cov  = (const float*)d_in[4];
    const float* nmin     = (const float*)d_in[5];
    const float* nmax     = (const float*)d_in[6];
    float* out = (float*)d_out;

    static int smem_set = 0;
    if (!smem_set) {
        cudaFuncSetAttribute(maha_kernel,
                             cudaFuncAttributeMaxDynamicSharedMemorySize,
                             58240);
        smem_set = 1;
    }

    prep_w_kernel<<<(DPAD * CC + 255) / 256, 256>>>(proj_w);
    prep_mean_kernel<<<dim3(NPOS / 32, 4), dim3(32, 8)>>>(mean);
    proj_kernel<<<dim3(16, BB), 128>>>(combined, proj_b);
    maha_kernel<<<NPOS, 128, 58240>>>(inv_cov);
    upsample_kernel<<<dim3(OHW * OHW / (256 * 4), BB), 256>>>(nmin, nmax, out);
}